// round 17
// baseline (speedup 1.0000x reference)
#include <cuda_runtime.h>

#define BB 16
#define LL 200
#define HH 64
#define NHEAD 2
#define PREP_ROWS 8
#define GRID_PREP (BB * LL / PREP_ROWS)   // 400
#define GRID_ATTN (BB * LL)               // 3200

__device__ float g_KpK[BB * LL * HH];
__device__ float g_VpV[BB * LL * HH];
__device__ unsigned g_prep_done = 0;
__device__ unsigned g_attn_done = 0;

__device__ __forceinline__ bool read_mask(const void* p, int i, int is_u8)
{
    return is_u8 ? (((const unsigned char*)p)[i] != 0)
                 : (((const int*)p)[i] != 0);
}

// ---------------------------------------------------------------------------
// Fused kernel. Blocks 0..399: prep (KpK = keys@Wk^T+bk+abs_pos_K,
// VpV = keys@Wv^T+bv+abs_pos_V), then signal g_prep_done.
// Blocks 400..3599: attention. Score split matches the reference's two
// einsums: partA=(tK+dK)*q (no prep dep; streams while prep runs), then a
// device-side wait on g_prep_done, then partB=KpK*q fixup from L2, softmax,
// V phase. Q row is computed locally per CTA (4096 FMAs).
// Deadlock safety: occ 8/SM -> wave 1 = 1184 CTAs includes all 400 prep
// CTAs, which never wait. Counters self-reset for graph replays.
// ---------------------------------------------------------------------------
__global__ __launch_bounds__(256, 8) void fused_kernel(
    const float* __restrict__ queries, const float* __restrict__ keys,
    const float* __restrict__ abs_pos_K, const float* __restrict__ abs_pos_V,
    const float* __restrict__ Wq, const float* __restrict__ bq_,
    const float* __restrict__ Wk, const float* __restrict__ bk_,
    const float* __restrict__ Wv, const float* __restrict__ bv_,
    const float* __restrict__ tK, const float* __restrict__ dK,
    const float* __restrict__ tV, const float* __restrict__ dV,
    const void* __restrict__ time_mask,
    const void* __restrict__ attn_mask,
    float* __restrict__ out)
{
    __shared__ __align__(16) char s_raw[18816];
    const int t = threadIdx.x;

    if (blockIdx.x < GRID_PREP) {
        // =================== PREP PATH ===================
        float  (*Ws)[HH + 1] = reinterpret_cast<float(*)[HH + 1]>(s_raw);   // 16640B
        float4 (*xk4)[16]    = reinterpret_cast<float4(*)[16]>(s_raw + 16640); // 2048B

        const int base_row = blockIdx.x * PREP_ROWS;
        if (t < PREP_ROWS * 16) {
            int r = t >> 4, j4 = t & 15;
            xk4[r][j4] = ((const float4*)keys)[(base_row + r) * 16 + j4];
        }
        const int c = t & 63;
        const int g = t >> 6;

        // ---- phase K: Wk ----
#pragma unroll
        for (int i = 0; i < 16; ++i) {
            int idx = i * 256 + t;
            Ws[idx >> 6][idx & 63] = Wk[idx];
        }
        __syncthreads();
        {
            float acck[2] = {0.f, 0.f};
#pragma unroll
            for (int j4 = 0; j4 < 16; ++j4) {
                float w0 = Ws[c][4 * j4 + 0], w1 = Ws[c][4 * j4 + 1];
                float w2 = Ws[c][4 * j4 + 2], w3 = Ws[c][4 * j4 + 3];
#pragma unroll
                for (int r = 0; r < 2; ++r) {
                    float4 xk = xk4[g * 2 + r][j4];
                    acck[r] += xk.x * w0 + xk.y * w1 + xk.z * w2 + xk.w * w3;
                }
            }
#pragma unroll
            for (int r = 0; r < 2; ++r) {
                int row = base_row + g * 2 + r;
                int o = row * HH + c;
                g_KpK[o] = acck[r] + bk_[c] + abs_pos_K[o];
            }
        }
        __syncthreads();   // all reads of Ws(K) done before overwrite

        // ---- phase V: Wv ----
#pragma unroll
        for (int i = 0; i < 16; ++i) {
            int idx = i * 256 + t;
            Ws[idx >> 6][idx & 63] = Wv[idx];
        }
        __syncthreads();
        {
            float accv[2] = {0.f, 0.f};
#pragma unroll
            for (int j4 = 0; j4 < 16; ++j4) {
                float w0 = Ws[c][4 * j4 + 0], w1 = Ws[c][4 * j4 + 1];
                float w2 = Ws[c][4 * j4 + 2], w3 = Ws[c][4 * j4 + 3];
#pragma unroll
                for (int r = 0; r < 2; ++r) {
                    float4 xk = xk4[g * 2 + r][j4];
                    accv[r] += xk.x * w0 + xk.y * w1 + xk.z * w2 + xk.w * w3;
                }
            }
#pragma unroll
            for (int r = 0; r < 2; ++r) {
                int row = base_row + g * 2 + r;
                int o = row * HH + c;
                g_VpV[o] = accv[r] + bv_[c] + abs_pos_V[o];
            }
        }
        __syncthreads();
        if (t == 0) { __threadfence(); atomicAdd(&g_prep_done, 1u); }
        return;
    }

    // =================== ATTENTION PATH ===================
    const int bq = blockIdx.x - GRID_PREP;
    const int b  = bq / LL;
    const int q  = bq % LL;
    const int warp = t >> 5;
    const int lane = t & 31;

    float4 (*s_red)[16] = reinterpret_cast<float4(*)[16]>(s_raw);          // 4096
    float  (*s_p)[LL]   = reinterpret_cast<float(*)[LL]>(s_raw + 4096);    // 1600
    float*  s_inv       = reinterpret_cast<float*>(s_raw + 5696);          // 8
    float*  s_q         = reinterpret_cast<float*>(s_raw + 5712);          // 256
    short*  s_idx       = reinterpret_cast<short*>(s_raw + 5968);          // 400
    int*    s_woff      = reinterpret_cast<int*>(s_raw + 6368);            // 32
    int*    s_misc      = reinterpret_cast<int*>(s_raw + 6400);            // M, is_u8

    // ---- local Q row (warps 0-1) and mask-dtype detection (warp 2) ----
    if (t < 64) {
        float acc = bq_[t];
        const float* qrow = queries + bq * HH;
        const float* wrow = Wq + t * HH;
#pragma unroll 8
        for (int j = 0; j < HH; ++j) acc += qrow[j] * wrow[j];
        s_q[t] = acc;
    } else if (t < 96) {
        // int32 storage: every word is 0/1; uint8 packs 4 bools -> word>1 a.s.
        unsigned w = ((const unsigned*)attn_mask)[t - 64];
        unsigned any = __ballot_sync(0xffffffffu, w > 1u);
        if (t == 64) s_misc[1] = (any != 0u) ? 1 : 0;
    }
    if (t == 0) s_misc[0] = 0;
    __syncthreads();
    const int  is_u8 = s_misc[1];
    const bool tmq   = read_mask(time_mask, bq, is_u8);

    // ---- deterministic stream compaction of unmasked k (skip if tmq) ----
    if (!tmq) {
        const int k = t;
        const bool valid = (k < LL) && !read_mask(attn_mask, q * LL + k, is_u8);
        const unsigned bal = __ballot_sync(0xffffffffu, valid);
        if (lane == 0) s_woff[warp] = __popc(bal);
        __syncthreads();
        if (t == 0) {
            int acc = 0;
#pragma unroll
            for (int w = 0; w < 8; ++w) { int c0 = s_woff[w]; s_woff[w] = acc; acc += c0; }
            s_misc[0] = acc;
        }
        __syncthreads();
        if (valid)
            s_idx[s_woff[warp] + __popc(bal & ((1u << lane) - 1u))] = (short)k;
    }
    __syncthreads();
    const int  M = s_misc[0];
    const bool uniform = (M == 0);        // tmq rows or fully-masked rows

    const float scale = 0.17677669529663687f;   // 1/sqrt(32)
    const int sub  = lane >> 4;
    const int idx4 = lane & 15;
    const int head = idx4 >> 3;
    const float4 q4 = ((const float4*)s_q)[idx4];

    // ---- K phase partA: (tK+dK)*q — no prep dependency; overlaps prep ----
    if (!uniform) {
        const float4* tK4 = (const float4*)tK + (size_t)bq * LL * 16;
        const float4* dK4 = (const float4*)dK + (size_t)bq * LL * 16;
        for (int jb = warp * 2; jb < M; jb += 16) {     // warp-uniform bound
            const int  j   = jb + sub;
            const bool act = (j < M);
            const int  kk  = s_idx[act ? j : jb];
            const int  o   = kk * 16 + idx4;
            float4 tv = __ldcs(tK4 + o);
            float4 dv = __ldcs(dK4 + o);
            float p = (tv.x + dv.x) * q4.x + (tv.y + dv.y) * q4.y
                    + (tv.z + dv.z) * q4.z + (tv.w + dv.w) * q4.w;
            p += __shfl_xor_sync(0xffffffffu, p, 1);
            p += __shfl_xor_sync(0xffffffffu, p, 2);
            p += __shfl_xor_sync(0xffffffffu, p, 4);
            if (act && (lane & 7) == 0) s_p[head][j] = p * scale;
        }
    }

    // ---- wait for prep output (g_KpK / g_VpV) ----
    __syncthreads();
    if (t == 0) {
        while (*((volatile unsigned*)&g_prep_done) < (unsigned)GRID_PREP)
            __nanosleep(100);
        __threadfence();
    }
    __syncthreads();

    // ---- K phase partB: += (KpK)*q from L2 ----
    if (!uniform) {
        const float4* KpK4 = (const float4*)g_KpK + b * LL * 16;
        for (int jb = warp * 2; jb < M; jb += 16) {
            const int  j   = jb + sub;
            const bool act = (j < M);
            const int  kk  = s_idx[act ? j : jb];
            float4 kp = KpK4[kk * 16 + idx4];
            float p = kp.x * q4.x + kp.y * q4.y + kp.z * q4.z + kp.w * q4.w;
            p += __shfl_xor_sync(0xffffffffu, p, 1);
            p += __shfl_xor_sync(0xffffffffu, p, 2);
            p += __shfl_xor_sync(0xffffffffu, p, 4);
            if (act && (lane & 7) == 0) s_p[head][j] += p * scale;
        }
    }
    __syncthreads();

    // ---- softmax over compacted entries: warp h handles head h ----
    if (!uniform && warp < NHEAD) {
        float m = -3.4e38f;
        for (int j = lane; j < M; j += 32) m = fmaxf(m, s_p[warp][j]);
#pragma unroll
        for (int s = 16; s > 0; s >>= 1)
            m = fmaxf(m, __shfl_xor_sync(0xffffffffu, m, s));
        float sum = 0.f;
        for (int j = lane; j < M; j += 32) {
            float e = __expf(s_p[warp][j] - m);
            s_p[warp][j] = e;
            sum += e;
        }
#pragma unroll
        for (int s = 16; s > 0; s >>= 1)
            sum += __shfl_xor_sync(0xffffffffu, sum, s);
        if (lane == 0) s_inv[warp] = 1.0f / sum;
    }
    __syncthreads();

    // ---- V phase ----
    {
        const int g = t >> 4;
        const float4* tV4  = (const float4*)tV + (size_t)bq * LL * 16;
        const float4* dV4  = (const float4*)dV + (size_t)bq * LL * 16;
        const float4* VpV4 = (const float4*)g_VpV + b * LL * 16;

        float4 acc = make_float4(0.f, 0.f, 0.f, 0.f);
        if (uniform) {
#pragma unroll 4
            for (int k = g; k < LL; k += 16) {
                const int o = k * 16 + idx4;
                float4 tv = __ldcs(tV4 + o);
                float4 dv = __ldcs(dV4 + o);
                float4 vp = VpV4[o];
                acc.x += tv.x + dv.x + vp.x;
                acc.y += tv.y + dv.y + vp.y;
                acc.z += tv.z + dv.z + vp.z;
                acc.w += tv.w + dv.w + vp.w;
            }
        } else {
#pragma unroll 4
            for (int j = g; j < M; j += 16) {
                const int kk = s_idx[j];
                const float a = s_p[head][j];
                const int o = kk * 16 + idx4;
                float4 tv = __ldcs(tV4 + o);
                float4 dv = __ldcs(dV4 + o);
                float4 vp = VpV4[o];
                acc.x += a * (tv.x + dv.x + vp.x);
                acc.y += a * (tv.y + dv.y + vp.y);
                acc.z += a * (tv.z + dv.z + vp.z);
                acc.w += a * (tv.w + dv.w + vp.w);
            }
        }
        s_red[t >> 4][idx4] = acc;
    }
    __syncthreads();

    if (t < HH) {
        const int i4 = t >> 2;
        const int c  = t & 3;
        const float inv = uniform ? (1.0f / LL) : s_inv[t >> 5];
        float sum = 0.f;
#pragma unroll
        for (int g2 = 0; g2 < 16; ++g2) {
            const float* v = (const float*)&s_red[g2][i4];
            sum += v[c];
        }
        out[bq * HH + t] = sum * inv;
    }

    // ---- completion counting: last attn CTA resets counters for replay ----
    __syncthreads();
    if (t == 0) {
        __threadfence();
        unsigned d = atomicAdd(&g_attn_done, 1u);
        if (d == (unsigned)(GRID_ATTN - 1)) {
            g_attn_done = 0u;
            g_prep_done = 0u;
            __threadfence();
        }
    }
}

// ---------------------------------------------------------------------------
extern "C" void kernel_launch(void* const* d_in, const int* in_sizes, int n_in,
                              void* d_out, int out_size)
{
    const float* queries  = (const float*)d_in[0];
    const float* keys     = (const float*)d_in[1];
    const void*  time_mask = d_in[2];
    const void*  attn_mask = d_in[3];
    const float* tK = (const float*)d_in[4];
    const float* tV = (const float*)d_in[5];
    const float* dK = (const float*)d_in[6];
    const float* dV = (const float*)d_in[7];
    const float* abs_pos_K = (const float*)d_in[8];
    const float* abs_pos_V = (const float*)d_in[9];
    const float* Wq = (const float*)d_in[10];
    const float* bq = (const float*)d_in[11];
    const float* Wk = (const float*)d_in[12];
    const float* bk = (const float*)d_in[13];
    const float* Wv = (const float*)d_in[14];
    const float* bv = (const float*)d_in[15];
    float* out = (float*)d_out;

    fused_kernel<<<GRID_PREP + GRID_ATTN, 256>>>(
        queries, keys, abs_pos_K, abs_pos_V,
        Wq, bq, Wk, bk, Wv, bv,
        tK, dK, tV, dV, time_mask, attn_mask, out);
}